// round 13
// baseline (speedup 1.0000x reference)
#include <cuda_runtime.h>

#define CC    10
#define NBIN  49
#define HH    34
#define WW    34
#define HW    (HH * WW)          // 1156
#define KDIM  (CC * NBIN)        // 490
#define NMAX  30000
#define BLK   512
#define TILES 4
#define CHUNK (BLK * TILES)      // 2048
#define KPAD  512                // padded k rows (>= 16*32)
#define NPADMAX (NMAX + 128)
#define SLC   (NBIN * HW)        // 56644

// Scratch (static device allocations are allowed)
__device__ float  g_out_t[KPAD * NPADMAX];   // [k][n] with runtime pitch NP
__device__ float4 g_ft8[NBIN * HW * 2];      // [bin][pos][c0..7] as 2x float4
__device__ float2 g_ft2[NBIN * HW];          // [bin][pos][c8..9]

// ---------------------------------------------------------------------------
// Kernel A: ft (C*49, 34, 34) -> channel-interleaved per-bin records.
// 3 threads per record (c0-3 / c4-7 / c8-9).
// ---------------------------------------------------------------------------
__global__ void k_prep(const float* __restrict__ ft) {
    int t = blockIdx.x * blockDim.x + threadIdx.x;   // over 3*49*1156
    if (t >= 3 * SLC) return;
    int g   = t / SLC;                // 0,1,2
    int idx = t - g * SLC;            // = bin*HW + p
    const float* s = ft + idx;
    if (g == 0) {
        float4 v;
        v.x = s[0 * SLC]; v.y = s[1 * SLC]; v.z = s[2 * SLC]; v.w = s[3 * SLC];
        g_ft8[idx * 2 + 0] = v;
    } else if (g == 1) {
        float4 v;
        v.x = s[4 * SLC]; v.y = s[5 * SLC]; v.z = s[6 * SLC]; v.w = s[7 * SLC];
        g_ft8[idx * 2 + 1] = v;
    } else {
        float2 v;
        v.x = s[8 * SLC]; v.y = s[9 * SLC];
        g_ft2[idx] = v;
    }
}

// ---------------------------------------------------------------------------
// Kernel B: one block = (bin, 4 roi-tiles of 512) within [nbase, nmax).
// Interior fast path: 0<=wstart<=31 && 0<=hstart<=31 => all taps in bounds,
// cnt=16, no bad11, floor-X0 in {0,1}. Else full reference edge path.
// ---------------------------------------------------------------------------
__global__ __launch_bounds__(BLK, 3) void k_roi(const float* __restrict__ rois,
                                                int nbase, int nmax, int NP) {
    __shared__ float4 smA[HW * 2];   // [pos][c0..7]
    __shared__ float2 smB[HW];       // [pos][c8..9]
    const int bin = blockIdx.y;

    {   // stage: contiguous float4 copies, conflict-free
        const float4* s8 = g_ft8 + bin * HW * 2;
        const float4* s2 = reinterpret_cast<const float4*>(g_ft2 + bin * HW);
        float4* d2 = reinterpret_cast<float4*>(smB);
        for (int i = threadIdx.x; i < HW * 2; i += BLK) smA[i] = s8[i];
        for (int i = threadIdx.x; i < HW / 2; i += BLK) d2[i] = s2[i];
    }
    __syncthreads();

    const int ph = bin / 7, pw = bin % 7;

#pragma unroll 1
    for (int tile = 0; tile < TILES; tile++) {
        const int n = nbase + (blockIdx.x * TILES + tile) * BLK + threadIdx.x;
        if (n >= nmax) break;

        float rsw = __ldg(rois + n * 5 + 1) * 0.125f;
        float rsh = __ldg(rois + n * 5 + 2) * 0.125f;
        float rew = __ldg(rois + n * 5 + 3) * 0.125f;
        float reh = __ldg(rois + n * 5 + 4) * 0.125f;
        float rh = reh - rsh; rh = (rh > 0.1f) ? rh : 0.1f;
        float rw = rew - rsw; rw = (rw > 0.1f) ? rw : 0.1f;
        float bsh = rh * (1.f / 7.f), bsw = rw * (1.f / 7.f);
        float sub_h = bsh * 0.25f, sub_w = bsw * 0.25f;
        float hstart = floorf(rsh + (float)ph * bsh);
        float wstart = floorf(rsw + (float)pw * bsw);

        const int X0 = (int)fminf(fmaxf(wstart, 0.f), (float)(WW - 3));
        const int Y0 = (int)fminf(fmaxf(hstart, 0.f), (float)(HH - 3));

        float W00, W01, W02, W10, W11, W12, W20, W21, W22;
        bool colx, rowx;

        bool interior = (wstart >= 0.f) && (wstart <= 31.f) &&
                        (hstart >= 0.f) && (hstart <= 31.f);

        if (interior) {
            // ---------- FAST PATH ------------------------------------------
            float Y0f = (float)Y0, X0f = (float)X0;
            float wyA0 = 0.f, wyA1 = 0.f, wyA2 = 0.f;
#pragma unroll
            for (int ih = 0; ih < 4; ih++) {
                float h = fmaf((float)ih + 0.5f, sub_h, hstart);
                float y1f = floorf(h);
                float dy = h - y1f;
                bool r1 = (y1f != Y0f);            // r==1 (else r==0)
                float ay = 1.f - dy;
                wyA0 += r1 ? 0.f : ay;
                wyA1 += r1 ? ay  : dy;
                wyA2 += r1 ? dy  : 0.f;
            }
            float wxA0 = 0.f, wxA1 = 0.f, wxA2 = 0.f;
#pragma unroll
            for (int iw = 0; iw < 4; iw++) {
                float w = fmaf((float)iw + 0.5f, sub_w, wstart);
                float x1f = floorf(w);
                float dx = w - x1f;
                bool r1 = (x1f != X0f);
                float ax = 1.f - dx;
                wxA0 += r1 ? 0.f : ax;
                wxA1 += r1 ? ax  : dx;
                wxA2 += r1 ? dx  : 0.f;
            }
            const float inv = 1.f / 16.f;
            float wy0 = wyA0 * inv, wy1 = wyA1 * inv, wy2 = wyA2 * inv;
            W00 = wy0 * wxA0; W01 = wy0 * wxA1; W02 = wy0 * wxA2;
            W10 = wy1 * wxA0; W11 = wy1 * wxA1; W12 = wy1 * wxA2;
            W20 = wy2 * wxA0; W21 = wy2 * wxA1; W22 = wy2 * wxA2;
            colx = (wxA2 != 0.f);
            rowx = (wyA2 != 0.f);
        } else {
            // ---------- EDGE PATH: full reference logic (rare) --------------
            float WY0 = 0.f, WY1 = 0.f, WY2 = 0.f;
            float CY0 = 0.f, CY1 = 0.f, CY2 = 0.f;
            float cntY = 0.f;
#pragma unroll
            for (int ih = 0; ih < 4; ih++) {
                float h = hstart + ((float)ih + 0.5f) * sub_h;
                bool hok = (h > -1.f) && (h < (float)HH);
                float y1f = floorf(h), y2f = ceilf(h);
                bool yv = ((y1f >= 0.f) && (y1f < (float)HH)) ||
                          ((y2f >= 0.f) && (y2f < (float)HH));
                float y1c = fminf(fmaxf(y1f, 0.f), 33.f);
                float y2c = fminf(fmaxf(y2f, 0.f), 33.f);
                float dy = h - y1c;
                int ry1 = (int)y1c - Y0;
                int ry2 = (int)y2c - Y0;
                float hokf = hok ? 1.f : 0.f;
                cntY += hokf;
                float ay = hokf * (1.f - dy), by = hokf * dy;
                WY0 += ((ry1 == 0) ? ay : 0.f) + ((ry2 == 0) ? by : 0.f);
                WY1 += ((ry1 == 1) ? ay : 0.f) + ((ry2 == 1) ? by : 0.f);
                WY2 += ((ry1 == 2) ? ay : 0.f) + ((ry2 == 2) ? by : 0.f);
                float cy = (hok && yv) ? (1.f - dy) : 0.f;
                CY0 += (ry1 == 0) ? cy : 0.f;
                CY1 += (ry1 == 1) ? cy : 0.f;
                CY2 += (ry1 == 2) ? cy : 0.f;
            }
            float WX0 = 0.f, WX1 = 0.f, WX2 = 0.f;
            float CX0 = 0.f, CX1 = 0.f, CX2 = 0.f;
            float cntX = 0.f;
#pragma unroll
            for (int iw = 0; iw < 4; iw++) {
                float w = wstart + ((float)iw + 0.5f) * sub_w;
                bool wok = (w > -1.f) && (w < (float)WW);
                float x1f = floorf(w), x2f = ceilf(w);
                bool badx = !((x1f >= 0.f) && (x1f < (float)WW)) ||
                            !((x2f >= 0.f) && (x2f < (float)WW));
                float x1c = fminf(fmaxf(x1f, 0.f), 33.f);
                float x2c = fminf(fmaxf(x2f, 0.f), 33.f);
                float dx = w - x1c;
                int cx1 = (int)x1c - X0;
                int cx2 = (int)x2c - X0;
                float wokf = wok ? 1.f : 0.f;
                cntX += wokf;
                float ax = wokf * (1.f - dx), bx = wokf * dx;
                WX0 += ((cx1 == 0) ? ax : 0.f) + ((cx2 == 0) ? bx : 0.f);
                WX1 += ((cx1 == 1) ? ax : 0.f) + ((cx2 == 1) ? bx : 0.f);
                WX2 += ((cx1 == 2) ? ax : 0.f) + ((cx2 == 2) ? bx : 0.f);
                float cx = (wok && badx) ? (1.f - dx) : 0.f;
                CX0 += (cx1 == 0) ? cx : 0.f;
                CX1 += (cx1 == 1) ? cx : 0.f;
                CX2 += (cx1 == 2) ? cx : 0.f;
            }
            float cnt = cntY * cntX;
            float inv = (cnt > 0.f) ? (1.f / cnt) : 1.f;
            float wy0 = WY0 * inv, wy1 = WY1 * inv, wy2 = WY2 * inv;
            W00 = fmaf(wy0, WX0, -CY0 * CX0 * inv);
            W01 = fmaf(wy0, WX1, -CY0 * CX1 * inv);
            W02 = fmaf(wy0, WX2, -CY0 * CX2 * inv);
            W10 = fmaf(wy1, WX0, -CY1 * CX0 * inv);
            W11 = fmaf(wy1, WX1, -CY1 * CX1 * inv);
            W12 = fmaf(wy1, WX2, -CY1 * CX2 * inv);
            W20 = fmaf(wy2, WX0, -CY2 * CX0 * inv);
            W21 = fmaf(wy2, WX1, -CY2 * CX1 * inv);
            W22 = fmaf(wy2, WX2, -CY2 * CX2 * inv);
            colx = (W02 != 0.f) || (W12 != 0.f) || (W22 != 0.f);
            rowx = (W20 != 0.f) || (W21 != 0.f) || (W22 != 0.f);
        }

        // ---- apply stencil (shared by both paths) ----
        float a0=0.f,a1=0.f,a2=0.f,a3=0.f,a4=0.f,a5=0.f,a6=0.f,a7=0.f,a8=0.f,a9=0.f;
        const int pbase = Y0 * WW + X0;

#define TEXEL(WGT, P) do {                                                  \
            float4 u0 = smA[(P) * 2];                                       \
            float4 u1 = smA[(P) * 2 + 1];                                   \
            float2 u2 = smB[(P)];                                           \
            a0 = fmaf((WGT), u0.x, a0); a1 = fmaf((WGT), u0.y, a1);         \
            a2 = fmaf((WGT), u0.z, a2); a3 = fmaf((WGT), u0.w, a3);         \
            a4 = fmaf((WGT), u1.x, a4); a5 = fmaf((WGT), u1.y, a5);         \
            a6 = fmaf((WGT), u1.z, a6); a7 = fmaf((WGT), u1.w, a7);         \
            a8 = fmaf((WGT), u2.x, a8); a9 = fmaf((WGT), u2.y, a9);         \
        } while (0)

        TEXEL(W00, pbase);
        TEXEL(W01, pbase + 1);
        TEXEL(W10, pbase + WW);
        TEXEL(W11, pbase + WW + 1);
        if (colx) { TEXEL(W02, pbase + 2); TEXEL(W12, pbase + WW + 2); }
        if (rowx) { TEXEL(W20, pbase + 2 * WW); TEXEL(W21, pbase + 2 * WW + 1); }
        if (colx && rowx) { TEXEL(W22, pbase + 2 * WW + 2); }
#undef TEXEL

        // Coalesced store to scratch [c*49+bin][n] with pitch NP
        g_out_t[(0 * NBIN + bin) * NP + n] = a0;
        g_out_t[(1 * NBIN + bin) * NP + n] = a1;
        g_out_t[(2 * NBIN + bin) * NP + n] = a2;
        g_out_t[(3 * NBIN + bin) * NP + n] = a3;
        g_out_t[(4 * NBIN + bin) * NP + n] = a4;
        g_out_t[(5 * NBIN + bin) * NP + n] = a5;
        g_out_t[(6 * NBIN + bin) * NP + n] = a6;
        g_out_t[(7 * NBIN + bin) * NP + n] = a7;
        g_out_t[(8 * NBIN + bin) * NP + n] = a8;
        g_out_t[(9 * NBIN + bin) * NP + n] = a9;
    }
}

// ---------------------------------------------------------------------------
// Kernel C: transpose scratch[k][n] -> out[n][k]. Tile 32k x 128n, 256 thr.
// Loads UNGUARDED (k padded to KPAD, n padded to pitch NP), MLP=4.
// nbase selects the n-origin so chunks can run in separate launches.
// ---------------------------------------------------------------------------
__global__ __launch_bounds__(256) void k_transpose_out(float* __restrict__ out,
                                                       int N, int NP, int nbase) {
    __shared__ float tile[32][133];
    const int n0 = nbase + blockIdx.x * 128;
    const int k0 = blockIdx.y * 32;
    const int tx = threadIdx.x & 31;     // n: 32 x float4 = 128
    const int ty = threadIdx.x >> 5;     // k: 8 rows per iter

#pragma unroll
    for (int i = 0; i < 4; i++) {
        int k = k0 + ty + 8 * i;
        float4 v = *reinterpret_cast<const float4*>(&g_out_t[(size_t)k * NP + n0 + tx * 4]);
        tile[ty + 8 * i][tx * 4 + 0] = v.x;
        tile[ty + 8 * i][tx * 4 + 1] = v.y;
        tile[ty + 8 * i][tx * 4 + 2] = v.z;
        tile[ty + 8 * i][tx * 4 + 3] = v.w;
    }
    __syncthreads();

    const int sx = threadIdx.x & 15;     // k: 16 x float2 = 32
    const int sy = threadIdx.x >> 4;     // n: 16 rows per iter
    const int k  = k0 + sx * 2;
    if (k < KDIM) {                       // KDIM even -> k+1 also in range
#pragma unroll
        for (int i = 0; i < 8; i++) {
            int n = n0 + sy + 16 * i;
            if (n < N) {
                float2 v;
                v.x = tile[sx * 2 + 0][sy + 16 * i];
                v.y = tile[sx * 2 + 1][sy + 16 * i];
                *reinterpret_cast<float2*>(&out[(size_t)n * KDIM + k]) = v;
            }
        }
    }
}

// ---------------------------------------------------------------------------
extern "C" void kernel_launch(void* const* d_in, const int* in_sizes, int n_in,
                              void* d_out, int out_size) {
    const float* ft   = (const float*)d_in[0];
    const float* rois = (const float*)d_in[1];
    float*       out  = (float*)d_out;
    int N = in_sizes[1] / 5;
    if (N > NMAX) N = NMAX;
    int NP = (N + 127) & ~127;           // 128-aligned pitch

    const dim3 TB(256);
    const int  KY = (KDIM + 31) / 32;    // 16 k-tiles

    k_prep<<<(3 * SLC + 255) / 256, 256>>>(ft);

    // Chunking: ~60/40 split in units of 2048 rois, sized for integral
    // blocks/SM waves (N=30000: 9 and 6 x-blocks -> 441 and 294 blocks).
    int nb_total = (N + CHUNK - 1) / CHUNK;
    int nb1 = (nb_total * 3) / 5;
    int C1 = nb1 * CHUNK;

    if (nb1 >= 1 && C1 < N) {
        // Fork: transpose(chunk1) in s2 overlaps roi(chunk2) in main stream.
        cudaStream_t s2;
        cudaStreamCreateWithFlags(&s2, cudaStreamNonBlocking);
        cudaEvent_t evA, evB;
        cudaEventCreateWithFlags(&evA, cudaEventDisableTiming);
        cudaEventCreateWithFlags(&evB, cudaEventDisableTiming);

        k_roi<<<dim3(nb1, NBIN), BLK>>>(rois, 0, C1, NP);          // chunk1
        cudaEventRecord(evA, 0);

        cudaStreamWaitEvent(s2, evA, 0);
        k_transpose_out<<<dim3(C1 / 128, KY), TB, 0, s2>>>(out, N, NP, 0);
        cudaEventRecord(evB, s2);

        int nb2 = (N - C1 + CHUNK - 1) / CHUNK;
        k_roi<<<dim3(nb2, NBIN), BLK>>>(rois, C1, N, NP);          // chunk2
        k_transpose_out<<<dim3((NP - C1) / 128, KY), TB>>>(out, N, NP, C1);

        cudaStreamWaitEvent(0, evB, 0);                            // join
    } else {
        // Fallback: serial path (small N)
        int nb = (N + CHUNK - 1) / CHUNK;
        k_roi<<<dim3(nb, NBIN), BLK>>>(rois, 0, N, NP);
        k_transpose_out<<<dim3(NP / 128, KY), TB>>>(out, N, NP, 0);
    }
}

// round 14
// speedup vs baseline: 1.0622x; 1.0622x over previous
#include <cuda_runtime.h>

#define CC    10
#define NBIN  49
#define HH    34
#define WW    34
#define HW    (HH * WW)          // 1156
#define KDIM  (CC * NBIN)        // 490
#define NMAX  30000
#define BLK   512
#define TILES 4
#define KPAD  512                // padded k rows (>= 16*32)
#define NPADMAX (NMAX + 128)
#define SLC   (NBIN * HW)        // 56644

// Scratch (static device allocations are allowed)
__device__ float  g_out_t[KPAD * NPADMAX];   // [k][n] with runtime pitch NP
__device__ float4 g_ft8[NBIN * HW * 2];      // [bin][pos][c0..7], halves
                                             // parity-swizzled (see k_prep)
__device__ float2 g_ft2[NBIN * HW];          // [bin][pos][c8..9]

// ---------------------------------------------------------------------------
// Kernel A: ft (C*49, 34, 34) -> channel-interleaved per-bin records.
// 3 threads per record. The two 16B halves of each record are SWAPPED for
// odd pos, so the gather's LDS.128 bank-quad starts span all 8 quads
// instead of 4 (conflict reduction in k_roi).
// ---------------------------------------------------------------------------
__global__ void k_prep(const float* __restrict__ ft) {
    int t = blockIdx.x * blockDim.x + threadIdx.x;   // over 3*49*1156
    if (t >= 3 * SLC) return;
    int g   = t / SLC;                // 0,1,2
    int idx = t - g * SLC;            // = bin*HW + p  (HW even -> idx&1 == p&1)
    const float* s = ft + idx;
    if (g == 0) {
        float4 v;
        v.x = s[0 * SLC]; v.y = s[1 * SLC]; v.z = s[2 * SLC]; v.w = s[3 * SLC];
        g_ft8[idx * 2 + (idx & 1)] = v;          // u0 half (swizzled)
    } else if (g == 1) {
        float4 v;
        v.x = s[4 * SLC]; v.y = s[5 * SLC]; v.z = s[6 * SLC]; v.w = s[7 * SLC];
        g_ft8[idx * 2 + 1 - (idx & 1)] = v;      // u1 half (swizzled)
    } else {
        float2 v;
        v.x = s[8 * SLC]; v.y = s[9 * SLC];
        g_ft2[idx] = v;
    }
}

// ---------------------------------------------------------------------------
// Kernel B: one block = (bin, 4 roi-tiles of 512), grid (15, 49), 3 CTAs/SM.
// Interior fast path: 0<=wstart<=31 && 0<=hstart<=31 => all taps in bounds,
// cnt=16, no bad11, floor-X0 in {0,1}. Else full reference edge path.
// ---------------------------------------------------------------------------
__global__ __launch_bounds__(BLK, 3) void k_roi(const float* __restrict__ rois,
                                                int N, int NP) {
    __shared__ float4 smA[HW * 2];   // [pos][c0..7], parity-swizzled halves
    __shared__ float2 smB[HW];       // [pos][c8..9]
    const int bin = blockIdx.y;

    {   // stage: contiguous float4 copies (swizzle preserved verbatim)
        const float4* s8 = g_ft8 + bin * HW * 2;
        const float4* s2 = reinterpret_cast<const float4*>(g_ft2 + bin * HW);
        float4* d2 = reinterpret_cast<float4*>(smB);
        for (int i = threadIdx.x; i < HW * 2; i += BLK) smA[i] = s8[i];
        for (int i = threadIdx.x; i < HW / 2; i += BLK) d2[i] = s2[i];
    }
    __syncthreads();

    const int ph = bin / 7, pw = bin % 7;

#pragma unroll 1
    for (int tile = 0; tile < TILES; tile++) {
        const int n = (blockIdx.x * TILES + tile) * BLK + threadIdx.x;
        if (n >= N) break;

        float rsw = __ldg(rois + n * 5 + 1) * 0.125f;
        float rsh = __ldg(rois + n * 5 + 2) * 0.125f;
        float rew = __ldg(rois + n * 5 + 3) * 0.125f;
        float reh = __ldg(rois + n * 5 + 4) * 0.125f;
        float rh = reh - rsh; rh = (rh > 0.1f) ? rh : 0.1f;
        float rw = rew - rsw; rw = (rw > 0.1f) ? rw : 0.1f;
        float bsh = rh * (1.f / 7.f), bsw = rw * (1.f / 7.f);
        float sub_h = bsh * 0.25f, sub_w = bsw * 0.25f;
        float hstart = floorf(rsh + (float)ph * bsh);
        float wstart = floorf(rsw + (float)pw * bsw);

        const int X0 = (int)fminf(fmaxf(wstart, 0.f), (float)(WW - 3));
        const int Y0 = (int)fminf(fmaxf(hstart, 0.f), (float)(HH - 3));

        float W00, W01, W02, W10, W11, W12, W20, W21, W22;
        bool colx, rowx;

        bool interior = (wstart >= 0.f) && (wstart <= 31.f) &&
                        (hstart >= 0.f) && (hstart <= 31.f);

        if (interior) {
            // ---------- FAST PATH ------------------------------------------
            float Y0f = (float)Y0, X0f = (float)X0;
            float wyA0 = 0.f, wyA1 = 0.f, wyA2 = 0.f;
#pragma unroll
            for (int ih = 0; ih < 4; ih++) {
                float h = fmaf((float)ih + 0.5f, sub_h, hstart);
                float y1f = floorf(h);
                float dy = h - y1f;
                bool r1 = (y1f != Y0f);            // r==1 (else r==0)
                float ay = 1.f - dy;
                wyA0 += r1 ? 0.f : ay;
                wyA1 += r1 ? ay  : dy;
                wyA2 += r1 ? dy  : 0.f;
            }
            float wxA0 = 0.f, wxA1 = 0.f, wxA2 = 0.f;
#pragma unroll
            for (int iw = 0; iw < 4; iw++) {
                float w = fmaf((float)iw + 0.5f, sub_w, wstart);
                float x1f = floorf(w);
                float dx = w - x1f;
                bool r1 = (x1f != X0f);
                float ax = 1.f - dx;
                wxA0 += r1 ? 0.f : ax;
                wxA1 += r1 ? ax  : dx;
                wxA2 += r1 ? dx  : 0.f;
            }
            const float inv = 1.f / 16.f;
            float wy0 = wyA0 * inv, wy1 = wyA1 * inv, wy2 = wyA2 * inv;
            W00 = wy0 * wxA0; W01 = wy0 * wxA1; W02 = wy0 * wxA2;
            W10 = wy1 * wxA0; W11 = wy1 * wxA1; W12 = wy1 * wxA2;
            W20 = wy2 * wxA0; W21 = wy2 * wxA1; W22 = wy2 * wxA2;
            colx = (wxA2 != 0.f);
            rowx = (wyA2 != 0.f);
        } else {
            // ---------- EDGE PATH: full reference logic (rare) --------------
            float WY0 = 0.f, WY1 = 0.f, WY2 = 0.f;
            float CY0 = 0.f, CY1 = 0.f, CY2 = 0.f;
            float cntY = 0.f;
#pragma unroll
            for (int ih = 0; ih < 4; ih++) {
                float h = hstart + ((float)ih + 0.5f) * sub_h;
                bool hok = (h > -1.f) && (h < (float)HH);
                float y1f = floorf(h), y2f = ceilf(h);
                bool yv = ((y1f >= 0.f) && (y1f < (float)HH)) ||
                          ((y2f >= 0.f) && (y2f < (float)HH));
                float y1c = fminf(fmaxf(y1f, 0.f), 33.f);
                float y2c = fminf(fmaxf(y2f, 0.f), 33.f);
                float dy = h - y1c;
                int ry1 = (int)y1c - Y0;
                int ry2 = (int)y2c - Y0;
                float hokf = hok ? 1.f : 0.f;
                cntY += hokf;
                float ay = hokf * (1.f - dy), by = hokf * dy;
                WY0 += ((ry1 == 0) ? ay : 0.f) + ((ry2 == 0) ? by : 0.f);
                WY1 += ((ry1 == 1) ? ay : 0.f) + ((ry2 == 1) ? by : 0.f);
                WY2 += ((ry1 == 2) ? ay : 0.f) + ((ry2 == 2) ? by : 0.f);
                float cy = (hok && yv) ? (1.f - dy) : 0.f;
                CY0 += (ry1 == 0) ? cy : 0.f;
                CY1 += (ry1 == 1) ? cy : 0.f;
                CY2 += (ry1 == 2) ? cy : 0.f;
            }
            float WX0 = 0.f, WX1 = 0.f, WX2 = 0.f;
            float CX0 = 0.f, CX1 = 0.f, CX2 = 0.f;
            float cntX = 0.f;
#pragma unroll
            for (int iw = 0; iw < 4; iw++) {
                float w = wstart + ((float)iw + 0.5f) * sub_w;
                bool wok = (w > -1.f) && (w < (float)WW);
                float x1f = floorf(w), x2f = ceilf(w);
                bool badx = !((x1f >= 0.f) && (x1f < (float)WW)) ||
                            !((x2f >= 0.f) && (x2f < (float)WW));
                float x1c = fminf(fmaxf(x1f, 0.f), 33.f);
                float x2c = fminf(fmaxf(x2f, 0.f), 33.f);
                float dx = w - x1c;
                int cx1 = (int)x1c - X0;
                int cx2 = (int)x2c - X0;
                float wokf = wok ? 1.f : 0.f;
                cntX += wokf;
                float ax = wokf * (1.f - dx), bx = wokf * dx;
                WX0 += ((cx1 == 0) ? ax : 0.f) + ((cx2 == 0) ? bx : 0.f);
                WX1 += ((cx1 == 1) ? ax : 0.f) + ((cx2 == 1) ? bx : 0.f);
                WX2 += ((cx1 == 2) ? ax : 0.f) + ((cx2 == 2) ? bx : 0.f);
                float cx = (wok && badx) ? (1.f - dx) : 0.f;
                CX0 += (cx1 == 0) ? cx : 0.f;
                CX1 += (cx1 == 1) ? cx : 0.f;
                CX2 += (cx1 == 2) ? cx : 0.f;
            }
            float cnt = cntY * cntX;
            float inv = (cnt > 0.f) ? (1.f / cnt) : 1.f;
            float wy0 = WY0 * inv, wy1 = WY1 * inv, wy2 = WY2 * inv;
            W00 = fmaf(wy0, WX0, -CY0 * CX0 * inv);
            W01 = fmaf(wy0, WX1, -CY0 * CX1 * inv);
            W02 = fmaf(wy0, WX2, -CY0 * CX2 * inv);
            W10 = fmaf(wy1, WX0, -CY1 * CX0 * inv);
            W11 = fmaf(wy1, WX1, -CY1 * CX1 * inv);
            W12 = fmaf(wy1, WX2, -CY1 * CX2 * inv);
            W20 = fmaf(wy2, WX0, -CY2 * CX0 * inv);
            W21 = fmaf(wy2, WX1, -CY2 * CX1 * inv);
            W22 = fmaf(wy2, WX2, -CY2 * CX2 * inv);
            colx = (W02 != 0.f) || (W12 != 0.f) || (W22 != 0.f);
            rowx = (W20 != 0.f) || (W21 != 0.f) || (W22 != 0.f);
        }

        // ---- apply stencil; smA halves are parity-swizzled ----
        float a0=0.f,a1=0.f,a2=0.f,a3=0.f,a4=0.f,a5=0.f,a6=0.f,a7=0.f,a8=0.f,a9=0.f;
        const int pbase = Y0 * WW + X0;

#define TEXEL(WGT, P) do {                                                  \
            int _s = (P) & 1;                                               \
            float4 u0 = smA[(P) * 2 + _s];                                  \
            float4 u1 = smA[(P) * 2 + 1 - _s];                              \
            float2 u2 = smB[(P)];                                           \
            a0 = fmaf((WGT), u0.x, a0); a1 = fmaf((WGT), u0.y, a1);         \
            a2 = fmaf((WGT), u0.z, a2); a3 = fmaf((WGT), u0.w, a3);         \
            a4 = fmaf((WGT), u1.x, a4); a5 = fmaf((WGT), u1.y, a5);         \
            a6 = fmaf((WGT), u1.z, a6); a7 = fmaf((WGT), u1.w, a7);         \
            a8 = fmaf((WGT), u2.x, a8); a9 = fmaf((WGT), u2.y, a9);         \
        } while (0)

        TEXEL(W00, pbase);
        TEXEL(W01, pbase + 1);
        TEXEL(W10, pbase + WW);
        TEXEL(W11, pbase + WW + 1);
        if (colx) { TEXEL(W02, pbase + 2); TEXEL(W12, pbase + WW + 2); }
        if (rowx) { TEXEL(W20, pbase + 2 * WW); TEXEL(W21, pbase + 2 * WW + 1); }
        if (colx && rowx) { TEXEL(W22, pbase + 2 * WW + 2); }
#undef TEXEL

        // Coalesced store to scratch [c*49+bin][n] with pitch NP
        g_out_t[(0 * NBIN + bin) * NP + n] = a0;
        g_out_t[(1 * NBIN + bin) * NP + n] = a1;
        g_out_t[(2 * NBIN + bin) * NP + n] = a2;
        g_out_t[(3 * NBIN + bin) * NP + n] = a3;
        g_out_t[(4 * NBIN + bin) * NP + n] = a4;
        g_out_t[(5 * NBIN + bin) * NP + n] = a5;
        g_out_t[(6 * NBIN + bin) * NP + n] = a6;
        g_out_t[(7 * NBIN + bin) * NP + n] = a7;
        g_out_t[(8 * NBIN + bin) * NP + n] = a8;
        g_out_t[(9 * NBIN + bin) * NP + n] = a9;
    }
}

// ---------------------------------------------------------------------------
// Kernel C: transpose scratch[k][n] -> out[n][k]. Tile 32k x 128n, 256 thr.
// Loads UNGUARDED (k padded to KPAD, n padded to pitch NP), MLP=4.
// ---------------------------------------------------------------------------
__global__ __launch_bounds__(256) void k_transpose_out(float* __restrict__ out,
                                                       int N, int NP) {
    __shared__ float tile[32][133];
    const int n0 = blockIdx.x * 128;
    const int k0 = blockIdx.y * 32;
    const int tx = threadIdx.x & 31;     // n: 32 x float4 = 128
    const int ty = threadIdx.x >> 5;     // k: 8 rows per iter

#pragma unroll
    for (int i = 0; i < 4; i++) {
        int k = k0 + ty + 8 * i;
        float4 v = *reinterpret_cast<const float4*>(&g_out_t[(size_t)k * NP + n0 + tx * 4]);
        tile[ty + 8 * i][tx * 4 + 0] = v.x;
        tile[ty + 8 * i][tx * 4 + 1] = v.y;
        tile[ty + 8 * i][tx * 4 + 2] = v.z;
        tile[ty + 8 * i][tx * 4 + 3] = v.w;
    }
    __syncthreads();

    const int sx = threadIdx.x & 15;     // k: 16 x float2 = 32
    const int sy = threadIdx.x >> 4;     // n: 16 rows per iter
    const int k  = k0 + sx * 2;
    if (k < KDIM) {                       // KDIM even -> k+1 also in range
#pragma unroll
        for (int i = 0; i < 8; i++) {
            int n = n0 + sy + 16 * i;
            if (n < N) {
                float2 v;
                v.x = tile[sx * 2 + 0][sy + 16 * i];
                v.y = tile[sx * 2 + 1][sy + 16 * i];
                *reinterpret_cast<float2*>(&out[(size_t)n * KDIM + k]) = v;
            }
        }
    }
}

// ---------------------------------------------------------------------------
extern "C" void kernel_launch(void* const* d_in, const int* in_sizes, int n_in,
                              void* d_out, int out_size) {
    const float* ft   = (const float*)d_in[0];
    const float* rois = (const float*)d_in[1];
    float*       out  = (float*)d_out;
    int N = in_sizes[1] / 5;
    if (N > NMAX) N = NMAX;
    int NP = (N + 127) & ~127;           // 128-aligned pitch

    k_prep<<<(3 * SLC + 255) / 256, 256>>>(ft);

    dim3 gb((N + BLK * TILES - 1) / (BLK * TILES), NBIN);
    k_roi<<<gb, BLK>>>(rois, N, NP);

    dim3 gc(NP / 128, (KDIM + 31) / 32);
    k_transpose_out<<<gc, 256>>>(out, N, NP);
}

// round 15
// speedup vs baseline: 1.0750x; 1.0121x over previous
#include <cuda_runtime.h>

#define CC    10
#define NBIN  49
#define HH    34
#define WW    34
#define HW    (HH * WW)          // 1156
#define KDIM  (CC * NBIN)        // 490
#define NMAX  30000
#define BLK   512
#define TILES 4
#define KPAD  512                // padded k rows (>= 16*32)
#define NPADMAX (NMAX + 128)
#define SLC   (NBIN * HW)        // 56644
#define RSTR  12                 // record stride in floats (48B)
#define SMEMB (HW * RSTR * 4)    // 55488 B dynamic smem

// Scratch (static device allocations are allowed)
__device__ float g_out_t[KPAD * NPADMAX];    // [k][n] with runtime pitch NP
__device__ float g_ftr[NBIN * HW * RSTR];    // [bin][pos][c0..9, pad2], 48B recs

// ---------------------------------------------------------------------------
// Kernel A: ft (C*49, 34, 34) -> 48B channel-interleaved per-bin records.
// 3 threads per record (c0-3 / c4-7 / c8-9). 48B stride => LDS.128 start
// bank-quad = (3*pos) mod 8 covers ALL 8 quads (conflict spread in k_roi).
// ---------------------------------------------------------------------------
__global__ void k_prep(const float* __restrict__ ft) {
    int t = blockIdx.x * blockDim.x + threadIdx.x;   // over 3*49*1156
    if (t >= 3 * SLC) return;
    int g   = t / SLC;                // 0,1,2
    int idx = t - g * SLC;            // = bin*HW + p
    const float* s = ft + idx;
    float* d = g_ftr + idx * RSTR;
    if (g == 0) {
        float4 v;
        v.x = s[0 * SLC]; v.y = s[1 * SLC]; v.z = s[2 * SLC]; v.w = s[3 * SLC];
        *reinterpret_cast<float4*>(d + 0) = v;
    } else if (g == 1) {
        float4 v;
        v.x = s[4 * SLC]; v.y = s[5 * SLC]; v.z = s[6 * SLC]; v.w = s[7 * SLC];
        *reinterpret_cast<float4*>(d + 4) = v;
    } else {
        float2 v;
        v.x = s[8 * SLC]; v.y = s[9 * SLC];
        *reinterpret_cast<float2*>(d + 8) = v;
    }
}

// ---------------------------------------------------------------------------
// Kernel B: one block = (bin, 4 roi-tiles of 512), grid (15, 49), 3 CTAs/SM.
// Dynamic smem: 1156 x 48B records. Interior fast path: 0<=wstart<=31 &&
// 0<=hstart<=31 => all taps in bounds, cnt=16, no bad11, floor-X0 in {0,1}.
// ---------------------------------------------------------------------------
__global__ __launch_bounds__(BLK, 3) void k_roi(const float* __restrict__ rois,
                                                int N, int NP) {
    extern __shared__ float smR[];   // [pos][12]
    const int bin = blockIdx.y;

    {   // stage: contiguous float4 copy, conflict-free
        const float4* s = reinterpret_cast<const float4*>(g_ftr + bin * HW * RSTR);
        float4* d = reinterpret_cast<float4*>(smR);
        for (int i = threadIdx.x; i < HW * (RSTR / 4); i += BLK) d[i] = s[i];
    }
    __syncthreads();

    const int ph = bin / 7, pw = bin % 7;

#pragma unroll 1
    for (int tile = 0; tile < TILES; tile++) {
        const int n = (blockIdx.x * TILES + tile) * BLK + threadIdx.x;
        if (n >= N) break;

        float rsw = __ldg(rois + n * 5 + 1) * 0.125f;
        float rsh = __ldg(rois + n * 5 + 2) * 0.125f;
        float rew = __ldg(rois + n * 5 + 3) * 0.125f;
        float reh = __ldg(rois + n * 5 + 4) * 0.125f;
        float rh = reh - rsh; rh = (rh > 0.1f) ? rh : 0.1f;
        float rw = rew - rsw; rw = (rw > 0.1f) ? rw : 0.1f;
        float bsh = rh * (1.f / 7.f), bsw = rw * (1.f / 7.f);
        float sub_h = bsh * 0.25f, sub_w = bsw * 0.25f;
        float hstart = floorf(rsh + (float)ph * bsh);
        float wstart = floorf(rsw + (float)pw * bsw);

        const int X0 = (int)fminf(fmaxf(wstart, 0.f), (float)(WW - 3));
        const int Y0 = (int)fminf(fmaxf(hstart, 0.f), (float)(HH - 3));

        float W00, W01, W02, W10, W11, W12, W20, W21, W22;
        bool colx, rowx;

        bool interior = (wstart >= 0.f) && (wstart <= 31.f) &&
                        (hstart >= 0.f) && (hstart <= 31.f);

        if (interior) {
            // ---------- FAST PATH ------------------------------------------
            float Y0f = (float)Y0, X0f = (float)X0;
            float wyA0 = 0.f, wyA1 = 0.f, wyA2 = 0.f;
#pragma unroll
            for (int ih = 0; ih < 4; ih++) {
                float h = fmaf((float)ih + 0.5f, sub_h, hstart);
                float y1f = floorf(h);
                float dy = h - y1f;
                bool r1 = (y1f != Y0f);            // r==1 (else r==0)
                float ay = 1.f - dy;
                wyA0 += r1 ? 0.f : ay;
                wyA1 += r1 ? ay  : dy;
                wyA2 += r1 ? dy  : 0.f;
            }
            float wxA0 = 0.f, wxA1 = 0.f, wxA2 = 0.f;
#pragma unroll
            for (int iw = 0; iw < 4; iw++) {
                float w = fmaf((float)iw + 0.5f, sub_w, wstart);
                float x1f = floorf(w);
                float dx = w - x1f;
                bool r1 = (x1f != X0f);
                float ax = 1.f - dx;
                wxA0 += r1 ? 0.f : ax;
                wxA1 += r1 ? ax  : dx;
                wxA2 += r1 ? dx  : 0.f;
            }
            const float inv = 1.f / 16.f;
            float wy0 = wyA0 * inv, wy1 = wyA1 * inv, wy2 = wyA2 * inv;
            W00 = wy0 * wxA0; W01 = wy0 * wxA1; W02 = wy0 * wxA2;
            W10 = wy1 * wxA0; W11 = wy1 * wxA1; W12 = wy1 * wxA2;
            W20 = wy2 * wxA0; W21 = wy2 * wxA1; W22 = wy2 * wxA2;
            colx = (wxA2 != 0.f);
            rowx = (wyA2 != 0.f);
        } else {
            // ---------- EDGE PATH: full reference logic (rare) --------------
            float WY0 = 0.f, WY1 = 0.f, WY2 = 0.f;
            float CY0 = 0.f, CY1 = 0.f, CY2 = 0.f;
            float cntY = 0.f;
#pragma unroll
            for (int ih = 0; ih < 4; ih++) {
                float h = hstart + ((float)ih + 0.5f) * sub_h;
                bool hok = (h > -1.f) && (h < (float)HH);
                float y1f = floorf(h), y2f = ceilf(h);
                bool yv = ((y1f >= 0.f) && (y1f < (float)HH)) ||
                          ((y2f >= 0.f) && (y2f < (float)HH));
                float y1c = fminf(fmaxf(y1f, 0.f), 33.f);
                float y2c = fminf(fmaxf(y2f, 0.f), 33.f);
                float dy = h - y1c;
                int ry1 = (int)y1c - Y0;
                int ry2 = (int)y2c - Y0;
                float hokf = hok ? 1.f : 0.f;
                cntY += hokf;
                float ay = hokf * (1.f - dy), by = hokf * dy;
                WY0 += ((ry1 == 0) ? ay : 0.f) + ((ry2 == 0) ? by : 0.f);
                WY1 += ((ry1 == 1) ? ay : 0.f) + ((ry2 == 1) ? by : 0.f);
                WY2 += ((ry1 == 2) ? ay : 0.f) + ((ry2 == 2) ? by : 0.f);
                float cy = (hok && yv) ? (1.f - dy) : 0.f;
                CY0 += (ry1 == 0) ? cy : 0.f;
                CY1 += (ry1 == 1) ? cy : 0.f;
                CY2 += (ry1 == 2) ? cy : 0.f;
            }
            float WX0 = 0.f, WX1 = 0.f, WX2 = 0.f;
            float CX0 = 0.f, CX1 = 0.f, CX2 = 0.f;
            float cntX = 0.f;
#pragma unroll
            for (int iw = 0; iw < 4; iw++) {
                float w = wstart + ((float)iw + 0.5f) * sub_w;
                bool wok = (w > -1.f) && (w < (float)WW);
                float x1f = floorf(w), x2f = ceilf(w);
                bool badx = !((x1f >= 0.f) && (x1f < (float)WW)) ||
                            !((x2f >= 0.f) && (x2f < (float)WW));
                float x1c = fminf(fmaxf(x1f, 0.f), 33.f);
                float x2c = fminf(fmaxf(x2f, 0.f), 33.f);
                float dx = w - x1c;
                int cx1 = (int)x1c - X0;
                int cx2 = (int)x2c - X0;
                float wokf = wok ? 1.f : 0.f;
                cntX += wokf;
                float ax = wokf * (1.f - dx), bx = wokf * dx;
                WX0 += ((cx1 == 0) ? ax : 0.f) + ((cx2 == 0) ? bx : 0.f);
                WX1 += ((cx1 == 1) ? ax : 0.f) + ((cx2 == 1) ? bx : 0.f);
                WX2 += ((cx1 == 2) ? ax : 0.f) + ((cx2 == 2) ? bx : 0.f);
                float cx = (wok && badx) ? (1.f - dx) : 0.f;
                CX0 += (cx1 == 0) ? cx : 0.f;
                CX1 += (cx1 == 1) ? cx : 0.f;
                CX2 += (cx1 == 2) ? cx : 0.f;
            }
            float cnt = cntY * cntX;
            float inv = (cnt > 0.f) ? (1.f / cnt) : 1.f;
            float wy0 = WY0 * inv, wy1 = WY1 * inv, wy2 = WY2 * inv;
            W00 = fmaf(wy0, WX0, -CY0 * CX0 * inv);
            W01 = fmaf(wy0, WX1, -CY0 * CX1 * inv);
            W02 = fmaf(wy0, WX2, -CY0 * CX2 * inv);
            W10 = fmaf(wy1, WX0, -CY1 * CX0 * inv);
            W11 = fmaf(wy1, WX1, -CY1 * CX1 * inv);
            W12 = fmaf(wy1, WX2, -CY1 * CX2 * inv);
            W20 = fmaf(wy2, WX0, -CY2 * CX0 * inv);
            W21 = fmaf(wy2, WX1, -CY2 * CX1 * inv);
            W22 = fmaf(wy2, WX2, -CY2 * CX2 * inv);
            colx = (W02 != 0.f) || (W12 != 0.f) || (W22 != 0.f);
            rowx = (W20 != 0.f) || (W21 != 0.f) || (W22 != 0.f);
        }

        // ---- apply stencil from 48B records ----
        float a0=0.f,a1=0.f,a2=0.f,a3=0.f,a4=0.f,a5=0.f,a6=0.f,a7=0.f,a8=0.f,a9=0.f;
        const int pbase = Y0 * WW + X0;

#define TEXEL(WGT, P) do {                                                  \
            const float* _t = smR + (P) * RSTR;                             \
            float4 u0 = *reinterpret_cast<const float4*>(_t);               \
            float4 u1 = *reinterpret_cast<const float4*>(_t + 4);           \
            float2 u2 = *reinterpret_cast<const float2*>(_t + 8);           \
            a0 = fmaf((WGT), u0.x, a0); a1 = fmaf((WGT), u0.y, a1);         \
            a2 = fmaf((WGT), u0.z, a2); a3 = fmaf((WGT), u0.w, a3);         \
            a4 = fmaf((WGT), u1.x, a4); a5 = fmaf((WGT), u1.y, a5);         \
            a6 = fmaf((WGT), u1.z, a6); a7 = fmaf((WGT), u1.w, a7);         \
            a8 = fmaf((WGT), u2.x, a8); a9 = fmaf((WGT), u2.y, a9);         \
        } while (0)

        TEXEL(W00, pbase);
        TEXEL(W01, pbase + 1);
        TEXEL(W10, pbase + WW);
        TEXEL(W11, pbase + WW + 1);
        if (colx) { TEXEL(W02, pbase + 2); TEXEL(W12, pbase + WW + 2); }
        if (rowx) { TEXEL(W20, pbase + 2 * WW); TEXEL(W21, pbase + 2 * WW + 1); }
        if (colx && rowx) { TEXEL(W22, pbase + 2 * WW + 2); }
#undef TEXEL

        // Coalesced store to scratch [c*49+bin][n] with pitch NP
        g_out_t[(0 * NBIN + bin) * NP + n] = a0;
        g_out_t[(1 * NBIN + bin) * NP + n] = a1;
        g_out_t[(2 * NBIN + bin) * NP + n] = a2;
        g_out_t[(3 * NBIN + bin) * NP + n] = a3;
        g_out_t[(4 * NBIN + bin) * NP + n] = a4;
        g_out_t[(5 * NBIN + bin) * NP + n] = a5;
        g_out_t[(6 * NBIN + bin) * NP + n] = a6;
        g_out_t[(7 * NBIN + bin) * NP + n] = a7;
        g_out_t[(8 * NBIN + bin) * NP + n] = a8;
        g_out_t[(9 * NBIN + bin) * NP + n] = a9;
    }
}

// ---------------------------------------------------------------------------
// Kernel C: transpose scratch[k][n] -> out[n][k]. Tile 32k x 128n, 256 thr.
// Loads UNGUARDED (k padded to KPAD, n padded to pitch NP), MLP=4.
// ---------------------------------------------------------------------------
__global__ __launch_bounds__(256) void k_transpose_out(float* __restrict__ out,
                                                       int N, int NP) {
    __shared__ float tile[32][133];
    const int n0 = blockIdx.x * 128;
    const int k0 = blockIdx.y * 32;
    const int tx = threadIdx.x & 31;     // n: 32 x float4 = 128
    const int ty = threadIdx.x >> 5;     // k: 8 rows per iter

#pragma unroll
    for (int i = 0; i < 4; i++) {
        int k = k0 + ty + 8 * i;
        float4 v = *reinterpret_cast<const float4*>(&g_out_t[(size_t)k * NP + n0 + tx * 4]);
        tile[ty + 8 * i][tx * 4 + 0] = v.x;
        tile[ty + 8 * i][tx * 4 + 1] = v.y;
        tile[ty + 8 * i][tx * 4 + 2] = v.z;
        tile[ty + 8 * i][tx * 4 + 3] = v.w;
    }
    __syncthreads();

    const int sx = threadIdx.x & 15;     // k: 16 x float2 = 32
    const int sy = threadIdx.x >> 4;     // n: 16 rows per iter
    const int k  = k0 + sx * 2;
    if (k < KDIM) {                       // KDIM even -> k+1 also in range
#pragma unroll
        for (int i = 0; i < 8; i++) {
            int n = n0 + sy + 16 * i;
            if (n < N) {
                float2 v;
                v.x = tile[sx * 2 + 0][sy + 16 * i];
                v.y = tile[sx * 2 + 1][sy + 16 * i];
                *reinterpret_cast<float2*>(&out[(size_t)n * KDIM + k]) = v;
            }
        }
    }
}

// ---------------------------------------------------------------------------
extern "C" void kernel_launch(void* const* d_in, const int* in_sizes, int n_in,
                              void* d_out, int out_size) {
    const float* ft   = (const float*)d_in[0];
    const float* rois = (const float*)d_in[1];
    float*       out  = (float*)d_out;
    int N = in_sizes[1] / 5;
    if (N > NMAX) N = NMAX;
    int NP = (N + 127) & ~127;           // 128-aligned pitch

    // Opt in to >48KB dynamic smem for k_roi (attribute call, not an alloc;
    // idempotent and capture-legal).
    cudaFuncSetAttribute(k_roi, cudaFuncAttributeMaxDynamicSharedMemorySize, SMEMB);

    k_prep<<<(3 * SLC + 255) / 256, 256>>>(ft);

    dim3 gb((N + BLK * TILES - 1) / (BLK * TILES), NBIN);
    k_roi<<<gb, BLK, SMEMB>>>(rois, N, NP);

    dim3 gc(NP / 128, (KDIM + 31) / 32);
    k_transpose_out<<<gc, 256>>>(out, N, NP);
}